// round 2
// baseline (speedup 1.0000x reference)
#include <cuda_runtime.h>
#include <math.h>

#define NB   256   // batch
#define CCH  64    // channels
#define INF  1024  // in features (32*32)
#define OUTF 1024  // out features

#define BM 128
#define BN 128
#define BK 32
#define SPAD 4     // smem row stride = BK + SPAD = 36 floats (bank-conflict-free frags)

// Scratch: sorted rows, layout [c][n][x] so GEMM A tiles are contiguous per channel.
__device__ float g_sorted[(size_t)CCH * NB * INF];

// ---------------------------------------------------------------------------
// Sort kernel: one warp per (n,c) row. 32 floats per thread in registers.
// Full bitonic network on 1024 elements, descending.
//   - stages with partner distance >= 32 elements: shfl.bfly across lanes
//   - stages with distance < 32: pure register compare-exchange
// ---------------------------------------------------------------------------
__global__ void sort_rows(const float* __restrict__ x) {
    const int warp_global = blockIdx.x * (blockDim.x >> 5) + (threadIdx.x >> 5);
    const int lane = threadIdx.x & 31;
    // warp_global in [0, NB*CCH)
    const int n = warp_global / CCH;
    const int c = warp_global % CCH;

    const float* src = x + ((size_t)n * CCH + c) * INF;

    float e[32];
    // blocked layout: element index i = lane*32 + r
    {
        const float4* s4 = (const float4*)(src + lane * 32);
        #pragma unroll
        for (int q = 0; q < 8; q++) {
            float4 v = s4[q];
            e[q * 4 + 0] = v.x; e[q * 4 + 1] = v.y;
            e[q * 4 + 2] = v.z; e[q * 4 + 3] = v.w;
        }
    }

    #pragma unroll
    for (int k = 2; k <= 1024; k <<= 1) {
        // cross-lane stages: j >= 32  (only when k >= 64)
        #pragma unroll
        for (int j = k >> 1; j >= 32; j >>= 1) {
            const int jj = j >> 5;  // lane distance
            const bool up = (((lane << 5) & k) == 0);   // k >= 64: depends on lane only
            const bool lower = ((lane & jj) == 0);
            const bool keep_max = (up == lower);        // descending network
            #pragma unroll
            for (int r = 0; r < 32; r++) {
                float v = __shfl_xor_sync(0xffffffffu, e[r], jj);
                e[r] = keep_max ? fmaxf(e[r], v) : fminf(e[r], v);
            }
        }
        // intra-thread stages: j < 32
        #pragma unroll
        for (int j = ((k >> 1) < 32 ? (k >> 1) : 16); j >= 1; j >>= 1) {
            #pragma unroll
            for (int r = 0; r < 32; r++) {
                if ((r & j) == 0) {
                    const int rr = r | j;
                    const bool up = ((((lane << 5) | r) & k) == 0);
                    float a = e[r], b = e[rr];
                    float mx = fmaxf(a, b), mn = fminf(a, b);
                    e[r]  = up ? mx : mn;   // descending block keeps max at low idx
                    e[rr] = up ? mn : mx;
                }
            }
        }
    }

    float* dst = g_sorted + ((size_t)c * NB + n) * INF + lane * 32;
    {
        float4* d4 = (float4*)dst;
        #pragma unroll
        for (int q = 0; q < 8; q++) {
            float4 v;
            v.x = e[q * 4 + 0]; v.y = e[q * 4 + 1];
            v.z = e[q * 4 + 2]; v.w = e[q * 4 + 3];
            d4[q] = v;
        }
    }
}

// ---------------------------------------------------------------------------
// Per-channel GEMM: Y[c][n][o] = sigmoid( sum_x Zs[c][n][x] * W[c][o][x] + b[c][o] )
// tf32 mma.sync m16n8k8, fp32 accumulate.
// Block tile 128x128, BK=32, 8 warps in 2x4 layout (warp tile 64x32).
// ---------------------------------------------------------------------------
__device__ __forceinline__ float f2tf(float f) {
    unsigned u;
    asm("cvt.rna.tf32.f32 %0, %1;" : "=r"(u) : "f"(f));
    return __uint_as_float(u);
}

__device__ __forceinline__ void mma_tf32(float* d, const unsigned* a, const unsigned* b) {
    asm volatile(
        "mma.sync.aligned.m16n8k8.row.col.f32.tf32.tf32.f32 "
        "{%0,%1,%2,%3}, {%4,%5,%6,%7}, {%8,%9}, {%0,%1,%2,%3};\n"
        : "+f"(d[0]), "+f"(d[1]), "+f"(d[2]), "+f"(d[3])
        : "r"(a[0]), "r"(a[1]), "r"(a[2]), "r"(a[3]),
          "r"(b[0]), "r"(b[1]));
}

__global__ __launch_bounds__(256) void gemm_tf32(const float* __restrict__ Wt,
                                                 const float* __restrict__ bias,
                                                 float* __restrict__ out) {
    const int c  = blockIdx.z;
    const int mt = blockIdx.y;   // 0..1   (n-batch tiles)
    const int nt = blockIdx.x;   // 0..7   (output-feature tiles)

    __shared__ float As[BM][BK + SPAD];
    __shared__ float Bs[BN][BK + SPAD];

    const float* Aptr = g_sorted + ((size_t)c * NB + mt * BM) * INF;
    const float* Bptr = Wt + ((size_t)c * OUTF + nt * BN) * INF;

    const int tid  = threadIdx.x;
    const int warp = tid >> 5, lane = tid & 31;
    const int wm = warp >> 2, wn = warp & 3;     // 2 x 4 warp grid
    const int g = lane >> 2, tig = lane & 3;

    float acc[4][4][4];
    #pragma unroll
    for (int mi = 0; mi < 4; mi++)
        #pragma unroll
        for (int ni = 0; ni < 4; ni++)
            #pragma unroll
            for (int q = 0; q < 4; q++) acc[mi][ni][q] = 0.f;

    // global -> smem loader mapping: 256 threads, each loads 4 float4 per tile
    const int lrow = tid >> 3;          // 0..31
    const int lcol = (tid & 7) << 2;    // 0,4,...,28

    // prefetch first K-tile into registers
    float4 ra[4], rb[4];
    #pragma unroll
    for (int r = 0; r < 4; r++) {
        ra[r] = *(const float4*)(Aptr + (size_t)(lrow + 32 * r) * INF + lcol);
        rb[r] = *(const float4*)(Bptr + (size_t)(lrow + 32 * r) * INF + lcol);
    }

    for (int k0 = 0; k0 < INF; k0 += BK) {
        // commit prefetched tile to smem (tf32-rounded)
        #pragma unroll
        for (int r = 0; r < 4; r++) {
            const int rowi = lrow + 32 * r;
            As[rowi][lcol + 0] = f2tf(ra[r].x);
            As[rowi][lcol + 1] = f2tf(ra[r].y);
            As[rowi][lcol + 2] = f2tf(ra[r].z);
            As[rowi][lcol + 3] = f2tf(ra[r].w);
            Bs[rowi][lcol + 0] = f2tf(rb[r].x);
            Bs[rowi][lcol + 1] = f2tf(rb[r].y);
            Bs[rowi][lcol + 2] = f2tf(rb[r].z);
            Bs[rowi][lcol + 3] = f2tf(rb[r].w);
        }
        __syncthreads();

        // prefetch next K-tile (overlaps with MMA below)
        const int kn = k0 + BK;
        if (kn < INF) {
            #pragma unroll
            for (int r = 0; r < 4; r++) {
                ra[r] = *(const float4*)(Aptr + (size_t)(lrow + 32 * r) * INF + kn + lcol);
                rb[r] = *(const float4*)(Bptr + (size_t)(lrow + 32 * r) * INF + kn + lcol);
            }
        }

        #pragma unroll
        for (int kk = 0; kk < BK; kk += 8) {
            unsigned a[4][4], b[4][2];
            #pragma unroll
            for (int mi = 0; mi < 4; mi++) {
                const int m = wm * 64 + mi * 16;
                a[mi][0] = __float_as_uint(As[m + g    ][kk + tig    ]);
                a[mi][1] = __float_as_uint(As[m + g + 8][kk + tig    ]);
                a[mi][2] = __float_as_uint(As[m + g    ][kk + tig + 4]);
                a[mi][3] = __float_as_uint(As[m + g + 8][kk + tig + 4]);
            }
            #pragma unroll
            for (int ni = 0; ni < 4; ni++) {
                const int nn = wn * 32 + ni * 8;
                b[ni][0] = __float_as_uint(Bs[nn + g][kk + tig    ]);
                b[ni][1] = __float_as_uint(Bs[nn + g][kk + tig + 4]);
            }
            #pragma unroll
            for (int mi = 0; mi < 4; mi++)
                #pragma unroll
                for (int ni = 0; ni < 4; ni++)
                    mma_tf32(acc[mi][ni], a[mi], b[ni]);
        }
        __syncthreads();
    }

    // epilogue: bias + sigmoid, scatter to out[n][c][o]
    #pragma unroll
    for (int mi = 0; mi < 4; mi++) {
        const int m0 = mt * BM + wm * 64 + mi * 16;
        const int r0 = m0 + g, r1 = m0 + g + 8;
        #pragma unroll
        for (int ni = 0; ni < 4; ni++) {
            const int o0 = nt * BN + wn * 32 + ni * 8 + 2 * tig;
            const float bv0 = bias[c * OUTF + o0];
            const float bv1 = bias[c * OUTF + o0 + 1];
            float v00 = acc[mi][ni][0] + bv0;
            float v01 = acc[mi][ni][1] + bv1;
            float v10 = acc[mi][ni][2] + bv0;
            float v11 = acc[mi][ni][3] + bv1;
            out[((size_t)r0 * CCH + c) * OUTF + o0    ] = 1.f / (1.f + expf(-v00));
            out[((size_t)r0 * CCH + c) * OUTF + o0 + 1] = 1.f / (1.f + expf(-v01));
            out[((size_t)r1 * CCH + c) * OUTF + o0    ] = 1.f / (1.f + expf(-v10));
            out[((size_t)r1 * CCH + c) * OUTF + o0 + 1] = 1.f / (1.f + expf(-v11));
        }
    }
}

extern "C" void kernel_launch(void* const* d_in, const int* in_sizes, int n_in,
                              void* d_out, int out_size) {
    const float* x  = (const float*)d_in[0];
    const float* Wt = (const float*)d_in[1];
    const float* b  = (const float*)d_in[2];
    float* out = (float*)d_out;

    // 16384 rows, 8 warps per block
    sort_rows<<<(NB * CCH) / 8, 256>>>(x);

    dim3 grid(OUTF / BN, NB / BM, CCH);
    gemm_tf32<<<grid, 256>>>(Wt, b, out);
}

// round 4
// speedup vs baseline: 1.9866x; 1.9866x over previous
#include <cuda_runtime.h>
#include <math.h>

#define NB   256   // batch
#define CCH  64    // channels
#define INF  1024  // in features (32*32)
#define OUTF 1024  // out features

#define BM 128
#define BN 128
#define BK 32
#define SPAD 4     // smem row stride = BK + SPAD = 36 floats

// Scratch: sorted rows, layout [c][n][x] so GEMM A tiles are contiguous per channel.
__device__ float g_sorted[(size_t)CCH * NB * INF];

// ---------------------------------------------------------------------------
// Bitonic sort, one warp per row, 32 elements/thread, blocked layout
// (element index i = lane*32 + r). ALL stage parameters are template
// constants so every e[] index is compile-time -> guaranteed registers.
// Descending order.
// ---------------------------------------------------------------------------
template<int K, int J>
__device__ __forceinline__ void bitonic_stage(float (&e)[32], int lane) {
    if constexpr (J >= 32) {
        // cross-lane stage: partner lane distance jj
        constexpr int jj = J >> 5;
        const bool up       = ((lane << 5) & K) == 0;   // K >= 64 here
        const bool lower    = (lane & jj) == 0;
        const bool keep_max = (up == lower);
        #pragma unroll
        for (int r = 0; r < 32; r++) {
            float v  = __shfl_xor_sync(0xffffffffu, e[r], jj);
            float mx = fmaxf(e[r], v);
            float mn = fminf(e[r], v);
            e[r] = keep_max ? mx : mn;
        }
    } else {
        // intra-thread stage. For K >= 32 the direction depends only on lane
        // (r bits never overlap K); for K <= 16 it depends only on r
        // (compile-time constant per pair).
        bool up_lane = true;
        if constexpr (K >= 32) up_lane = (((lane << 5) & K) == 0);
        #pragma unroll
        for (int r = 0; r < 32; r++) {
            if ((r & J) == 0) {
                const int rr = r | J;
                bool up;
                if constexpr (K <= 16) up = ((r & K) == 0);
                else                   up = up_lane;
                float a = e[r], b = e[rr];
                float mx = fmaxf(a, b);
                float mn = fminf(a, b);
                e[r]  = up ? mx : mn;
                e[rr] = up ? mn : mx;
            }
        }
    }
}

template<int K, int J>
__device__ __forceinline__ void bitonic_merge(float (&e)[32], int lane) {
    bitonic_stage<K, J>(e, lane);
    if constexpr (J > 1) bitonic_merge<K, (J >> 1)>(e, lane);
}

template<int K>
__device__ __forceinline__ void bitonic_level(float (&e)[32], int lane) {
    bitonic_merge<K, (K >> 1)>(e, lane);
    if constexpr (K < 1024) bitonic_level<(K << 1)>(e, lane);
}

__global__ __launch_bounds__(256) void sort_rows(const float* __restrict__ x) {
    const int warp_global = blockIdx.x * (blockDim.x >> 5) + (threadIdx.x >> 5);
    const int lane = threadIdx.x & 31;
    const int n = warp_global / CCH;
    const int c = warp_global % CCH;

    const float* src = x + ((size_t)n * CCH + c) * INF;

    float e[32];
    {
        const float4* s4 = (const float4*)(src + lane * 32);
        #pragma unroll
        for (int q = 0; q < 8; q++) {
            float4 v = s4[q];
            e[q * 4 + 0] = v.x; e[q * 4 + 1] = v.y;
            e[q * 4 + 2] = v.z; e[q * 4 + 3] = v.w;
        }
    }

    bitonic_level<2>(e, lane);

    float* dst = g_sorted + ((size_t)c * NB + n) * INF + lane * 32;
    {
        float4* d4 = (float4*)dst;
        #pragma unroll
        for (int q = 0; q < 8; q++) {
            float4 v;
            v.x = e[q * 4 + 0]; v.y = e[q * 4 + 1];
            v.z = e[q * 4 + 2]; v.w = e[q * 4 + 3];
            d4[q] = v;
        }
    }
}

// ---------------------------------------------------------------------------
// Per-channel GEMM: Y[c][n][o] = sigmoid( sum_x Zs[c][n][x] * W[c][o][x] + b[c][o] )
// tf32 mma.sync m16n8k8, fp32 accumulate.
// 128x128 block tile, BK=32, DOUBLE-BUFFERED smem (one sync per K-tile).
// ---------------------------------------------------------------------------
__device__ __forceinline__ float f2tf(float f) {
    unsigned u;
    asm("cvt.rna.tf32.f32 %0, %1;" : "=r"(u) : "f"(f));
    return __uint_as_float(u);
}

__device__ __forceinline__ void mma_tf32(float* d, const unsigned* a, const unsigned* b) {
    asm volatile(
        "mma.sync.aligned.m16n8k8.row.col.f32.tf32.tf32.f32 "
        "{%0,%1,%2,%3}, {%4,%5,%6,%7}, {%8,%9}, {%0,%1,%2,%3};\n"
        : "+f"(d[0]), "+f"(d[1]), "+f"(d[2]), "+f"(d[3])
        : "r"(a[0]), "r"(a[1]), "r"(a[2]), "r"(a[3]),
          "r"(b[0]), "r"(b[1]));
}

#define TSTRIDE (BK + SPAD)
#define TILE_FLOATS (BM * TSTRIDE)

__global__ __launch_bounds__(256, 1) void gemm_tf32(const float* __restrict__ Wt,
                                                    const float* __restrict__ bias,
                                                    float* __restrict__ out) {
    extern __shared__ float smem[];
    float* As = smem;                       // [2][BM][TSTRIDE]
    float* Bs = smem + 2 * TILE_FLOATS;     // [2][BN][TSTRIDE]

    const int c  = blockIdx.z;
    const int mt = blockIdx.y;   // 0..1
    const int nt = blockIdx.x;   // 0..7

    const float* Aptr = g_sorted + ((size_t)c * NB + mt * BM) * INF;
    const float* Bptr = Wt + ((size_t)c * OUTF + nt * BN) * INF;

    const int tid  = threadIdx.x;
    const int warp = tid >> 5, lane = tid & 31;
    const int wm = warp >> 2, wn = warp & 3;     // 2 x 4 warp grid
    const int g = lane >> 2, tig = lane & 3;

    float acc[4][4][4];
    #pragma unroll
    for (int mi = 0; mi < 4; mi++)
        #pragma unroll
        for (int ni = 0; ni < 4; ni++)
            #pragma unroll
            for (int q = 0; q < 4; q++) acc[mi][ni][q] = 0.f;

    // loader mapping: each thread loads 4 float4 per matrix tile
    const int lrow = tid >> 3;          // 0..31
    const int lcol = (tid & 7) << 2;    // 0,4,...,28

    float4 ra[4], rb[4];

    // prefetch tile 0
    #pragma unroll
    for (int r = 0; r < 4; r++) {
        ra[r] = *(const float4*)(Aptr + (size_t)(lrow + 32 * r) * INF + lcol);
        rb[r] = *(const float4*)(Bptr + (size_t)(lrow + 32 * r) * INF + lcol);
    }
    // commit tile 0 into buffer 0
    #pragma unroll
    for (int r = 0; r < 4; r++) {
        const int rowi = lrow + 32 * r;
        float* a = As + rowi * TSTRIDE + lcol;
        float* b = Bs + rowi * TSTRIDE + lcol;
        a[0] = f2tf(ra[r].x); a[1] = f2tf(ra[r].y); a[2] = f2tf(ra[r].z); a[3] = f2tf(ra[r].w);
        b[0] = f2tf(rb[r].x); b[1] = f2tf(rb[r].y); b[2] = f2tf(rb[r].z); b[3] = f2tf(rb[r].w);
    }
    __syncthreads();

    const int NT = INF / BK;   // 32
    for (int t = 0; t < NT; t++) {
        const int buf  = t & 1;
        const int nbuf = buf ^ 1;
        const bool has_next = (t + 1 < NT);

        // issue next tile's global loads early (overlap with MMA below)
        if (has_next) {
            const int kn = (t + 1) * BK;
            #pragma unroll
            for (int r = 0; r < 4; r++) {
                ra[r] = *(const float4*)(Aptr + (size_t)(lrow + 32 * r) * INF + kn + lcol);
                rb[r] = *(const float4*)(Bptr + (size_t)(lrow + 32 * r) * INF + kn + lcol);
            }
        }

        const float* Ab = As + buf * TILE_FLOATS;
        const float* Bb = Bs + buf * TILE_FLOATS;

        #pragma unroll
        for (int kk = 0; kk < BK; kk += 8) {
            unsigned a[4][4], b[4][2];
            #pragma unroll
            for (int mi = 0; mi < 4; mi++) {
                const int m = wm * 64 + mi * 16;
                a[mi][0] = __float_as_uint(Ab[(m + g    ) * TSTRIDE + kk + tig    ]);
                a[mi][1] = __float_as_uint(Ab[(m + g + 8) * TSTRIDE + kk + tig    ]);
                a[mi][2] = __float_as_uint(Ab[(m + g    ) * TSTRIDE + kk + tig + 4]);
                a[mi][3] = __float_as_uint(Ab[(m + g + 8) * TSTRIDE + kk + tig + 4]);
            }
            #pragma unroll
            for (int ni = 0; ni < 4; ni++) {
                const int nn = wn * 32 + ni * 8;
                b[ni][0] = __float_as_uint(Bb[(nn + g) * TSTRIDE + kk + tig    ]);
                b[ni][1] = __float_as_uint(Bb[(nn + g) * TSTRIDE + kk + tig + 4]);
            }
            #pragma unroll
            for (int mi = 0; mi < 4; mi++)
                #pragma unroll
                for (int ni = 0; ni < 4; ni++)
                    mma_tf32(acc[mi][ni], a[mi], b[ni]);
        }

        // commit next tile into the other buffer (its last readers sync'ed
        // at the end of iteration t-1, so this is safe without a pre-sync)
        if (has_next) {
            float* An = As + nbuf * TILE_FLOATS;
            float* Bn = Bs + nbuf * TILE_FLOATS;
            #pragma unroll
            for (int r = 0; r < 4; r++) {
                const int rowi = lrow + 32 * r;
                float* a = An + rowi * TSTRIDE + lcol;
                float* b = Bn + rowi * TSTRIDE + lcol;
                a[0] = f2tf(ra[r].x); a[1] = f2tf(ra[r].y); a[2] = f2tf(ra[r].z); a[3] = f2tf(ra[r].w);
                b[0] = f2tf(rb[r].x); b[1] = f2tf(rb[r].y); b[2] = f2tf(rb[r].z); b[3] = f2tf(rb[r].w);
            }
        }
        __syncthreads();
    }

    // epilogue: bias + sigmoid, scatter to out[n][c][o]
    #pragma unroll
    for (int mi = 0; mi < 4; mi++) {
        const int m0 = mt * BM + wm * 64 + mi * 16;
        const int r0 = m0 + g, r1 = m0 + g + 8;
        #pragma unroll
        for (int ni = 0; ni < 4; ni++) {
            const int o0 = nt * BN + wn * 32 + ni * 8 + 2 * tig;
            const float bv0 = __ldg(bias + c * OUTF + o0);
            const float bv1 = __ldg(bias + c * OUTF + o0 + 1);
            float v00 = acc[mi][ni][0] + bv0;
            float v01 = acc[mi][ni][1] + bv1;
            float v10 = acc[mi][ni][2] + bv0;
            float v11 = acc[mi][ni][3] + bv1;
            out[((size_t)r0 * CCH + c) * OUTF + o0    ] = 1.f / (1.f + __expf(-v00));
            out[((size_t)r0 * CCH + c) * OUTF + o0 + 1] = 1.f / (1.f + __expf(-v01));
            out[((size_t)r1 * CCH + c) * OUTF + o0    ] = 1.f / (1.f + __expf(-v10));
            out[((size_t)r1 * CCH + c) * OUTF + o0 + 1] = 1.f / (1.f + __expf(-v11));
        }
    }
}

extern "C" void kernel_launch(void* const* d_in, const int* in_sizes, int n_in,
                              void* d_out, int out_size) {
    const float* x  = (const float*)d_in[0];
    const float* Wt = (const float*)d_in[1];
    const float* b  = (const float*)d_in[2];
    float* out = (float*)d_out;

    sort_rows<<<(NB * CCH) / 8, 256>>>(x);

    static bool attr_set = false;
    const int smem_bytes = 4 * TILE_FLOATS * sizeof(float);   // 73728
    if (!attr_set) {
        cudaFuncSetAttribute(gemm_tf32, cudaFuncAttributeMaxDynamicSharedMemorySize,
                             smem_bytes);
        attr_set = true;
    }

    dim3 grid(OUTF / BN, NB / BM, CCH);
    gemm_tf32<<<grid, 256, smem_bytes>>>(Wt, b, out);
}

// round 7
// speedup vs baseline: 2.2749x; 1.1451x over previous
#include <cuda_runtime.h>
#include <math.h>
#include <stdint.h>

#define NB   256   // batch
#define CCH  64    // channels
#define INF  1024  // in features
#define OUTF 1024  // out features

#define BM 128
#define BN 128
#define BK 32
#define SPAD 4
#define TSTRIDE (BK + SPAD)   // 36 floats

// Scratch: sorted rows (tf32-pre-rounded), layout [c][n][x].
__device__ float g_sorted[(size_t)CCH * NB * INF];

__device__ __forceinline__ float f2tf(float f) {
    unsigned u;
    asm("cvt.rna.tf32.f32 %0, %1;" : "=r"(u) : "f"(f));
    return __uint_as_float(u);
}

// ===========================================================================
// Sort: one warp per row, 32 elems/thread, fully-templated bitonic network.
// Writes tf32-rounded values (A-side cvt hoisted out of the GEMM).
// ===========================================================================
template<int K, int J>
__device__ __forceinline__ void bitonic_stage(float (&e)[32], int lane) {
    if constexpr (J >= 32) {
        constexpr int jj = J >> 5;
        const bool up       = ((lane << 5) & K) == 0;
        const bool lower    = (lane & jj) == 0;
        const bool keep_max = (up == lower);
        #pragma unroll
        for (int r = 0; r < 32; r++) {
            float v  = __shfl_xor_sync(0xffffffffu, e[r], jj);
            float mx = fmaxf(e[r], v);
            float mn = fminf(e[r], v);
            e[r] = keep_max ? mx : mn;
        }
    } else {
        bool up_lane = true;
        if constexpr (K >= 32) up_lane = (((lane << 5) & K) == 0);
        #pragma unroll
        for (int r = 0; r < 32; r++) {
            if ((r & J) == 0) {
                const int rr = r | J;
                bool up;
                if constexpr (K <= 16) up = ((r & K) == 0);
                else                   up = up_lane;
                float a = e[r], b = e[rr];
                float mx = fmaxf(a, b);
                float mn = fminf(a, b);
                e[r]  = up ? mx : mn;
                e[rr] = up ? mn : mx;
            }
        }
    }
}

template<int K, int J>
__device__ __forceinline__ void bitonic_merge(float (&e)[32], int lane) {
    bitonic_stage<K, J>(e, lane);
    if constexpr (J > 1) bitonic_merge<K, (J >> 1)>(e, lane);
}

template<int K>
__device__ __forceinline__ void bitonic_level(float (&e)[32], int lane) {
    bitonic_merge<K, (K >> 1)>(e, lane);
    if constexpr (K < 1024) bitonic_level<(K << 1)>(e, lane);
}

__global__ __launch_bounds__(256) void sort_rows(const float* __restrict__ x) {
    const int warp_global = blockIdx.x * (blockDim.x >> 5) + (threadIdx.x >> 5);
    const int lane = threadIdx.x & 31;
    const int n = warp_global / CCH;
    const int c = warp_global % CCH;

    const float* src = x + ((size_t)n * CCH + c) * INF;

    float e[32];
    {
        const float4* s4 = (const float4*)(src + lane * 32);
        #pragma unroll
        for (int q = 0; q < 8; q++) {
            float4 v = s4[q];
            e[q * 4 + 0] = v.x; e[q * 4 + 1] = v.y;
            e[q * 4 + 2] = v.z; e[q * 4 + 3] = v.w;
        }
    }

    bitonic_level<2>(e, lane);

    float* dst = g_sorted + ((size_t)c * NB + n) * INF + lane * 32;
    {
        float4* d4 = (float4*)dst;
        #pragma unroll
        for (int q = 0; q < 8; q++) {
            float4 v;
            v.x = f2tf(e[q * 4 + 0]); v.y = f2tf(e[q * 4 + 1]);
            v.z = f2tf(e[q * 4 + 2]); v.w = f2tf(e[q * 4 + 3]);
            d4[q] = v;
        }
    }
}

// ===========================================================================
// Per-channel GEMM, tf32 mma.sync m16n8k8, ldmatrix fragment loads.
// 128x128 block tile, BK=32, single-buffered smem, 2 CTAs/SM.
// ===========================================================================
__device__ __forceinline__ void mma_tf32(float* d, const unsigned* a, const unsigned* b) {
    asm volatile(
        "mma.sync.aligned.m16n8k8.row.col.f32.tf32.tf32.f32 "
        "{%0,%1,%2,%3}, {%4,%5,%6,%7}, {%8,%9}, {%0,%1,%2,%3};\n"
        : "+f"(d[0]), "+f"(d[1]), "+f"(d[2]), "+f"(d[3])
        : "r"(a[0]), "r"(a[1]), "r"(a[2]), "r"(a[3]),
          "r"(b[0]), "r"(b[1]));
}

#define LDSM_X4(r0, r1, r2, r3, addr)                                          \
    asm volatile("ldmatrix.sync.aligned.m8n8.x4.shared.b16 {%0,%1,%2,%3}, [%4];" \
                 : "=r"(r0), "=r"(r1), "=r"(r2), "=r"(r3) : "r"(addr))

__device__ __forceinline__ uint32_t smem_u32(const void* p) {
    uint32_t a;
    asm("{ .reg .u64 t; cvta.to.shared.u64 t, %1; cvt.u32.u64 %0, t; }" : "=r"(a) : "l"(p));
    return a;
}

__global__ __launch_bounds__(256, 2) void gemm_tf32(const float* __restrict__ Wt,
                                                    const float* __restrict__ bias,
                                                    float* __restrict__ out) {
    __shared__ float As[BM][TSTRIDE];
    __shared__ float Bs[BN][TSTRIDE];

    const int c  = blockIdx.z;
    const int mt = blockIdx.y;   // 0..1
    const int nt = blockIdx.x;   // 0..7

    const float* Aptr = g_sorted + ((size_t)c * NB + (size_t)mt * BM) * INF;
    const float* Bptr = Wt + ((size_t)c * OUTF + (size_t)nt * BN) * INF;

    const int tid  = threadIdx.x;
    const int warp = tid >> 5, lane = tid & 31;
    const int wm = warp >> 2, wn = warp & 3;     // 2 x 4 warp grid
    const int g = lane >> 2, tig = lane & 3;

    float acc[4][4][4];
    #pragma unroll
    for (int mi = 0; mi < 4; mi++)
        #pragma unroll
        for (int ni = 0; ni < 4; ni++)
            #pragma unroll
            for (int q = 0; q < 4; q++) acc[mi][ni][q] = 0.f;

    // ldmatrix per-lane row addresses (bytes into smem)
    // A (mi-th 16x8 fragment): matrices {rows 0-7,c0-3},{rows 8-15,c0-3},{rows 0-7,c4-7},{rows 8-15,c4-7}
    const uint32_t As_base = smem_u32(As);
    const uint32_t Bs_base = smem_u32(Bs);
    const int a_row = (lane & 7) + ((lane >> 3) & 1) * 8;
    const int a_kq  = (lane >> 4) * 4;
    uint32_t a_addr[4];
    #pragma unroll
    for (int mi = 0; mi < 4; mi++)
        a_addr[mi] = As_base + (uint32_t)(((wm * 64 + mi * 16 + a_row) * TSTRIDE + a_kq) * 4);
    // B (nj-th pair of 8x8 n-fragments): matrices {n0-7,c0-3},{n0-7,c4-7},{n8-15,c0-3},{n8-15,c4-7}
    const int b_q   = lane >> 3;
    const int b_row = (lane & 7) + (b_q >> 1) * 8;
    const int b_kq  = (b_q & 1) * 4;
    uint32_t b_addr[2];
    #pragma unroll
    for (int nj = 0; nj < 2; nj++)
        b_addr[nj] = Bs_base + (uint32_t)(((wn * 32 + nj * 16 + b_row) * TSTRIDE + b_kq) * 4);

    // loader mapping: thread loads 4 float4 per matrix per tile
    const int lrow = tid >> 3;          // 0..31
    const int lcol = (tid & 7) << 2;    // 0,4,...,28

    float4 ra[4], rb[4];
    #pragma unroll
    for (int r = 0; r < 4; r++) {
        ra[r] = *(const float4*)(Aptr + (size_t)(lrow + 32 * r) * INF + lcol);
        rb[r] = *(const float4*)(Bptr + (size_t)(lrow + 32 * r) * INF + lcol);
    }

    const int NT = INF / BK;   // 32
    for (int t = 0; t < NT; t++) {
        // commit current tile (A already tf32; B converted here)
        #pragma unroll
        for (int r = 0; r < 4; r++) {
            const int rowi = lrow + 32 * r;
            *(float4*)&As[rowi][lcol] = ra[r];
            float4 v = rb[r];
            v.x = f2tf(v.x); v.y = f2tf(v.y); v.z = f2tf(v.z); v.w = f2tf(v.w);
            *(float4*)&Bs[rowi][lcol] = v;
        }
        __syncthreads();

        // prefetch next tile (overlaps MMA)
        if (t + 1 < NT) {
            const int kn = (t + 1) * BK;
            #pragma unroll
            for (int r = 0; r < 4; r++) {
                ra[r] = *(const float4*)(Aptr + (size_t)(lrow + 32 * r) * INF + kn + lcol);
                rb[r] = *(const float4*)(Bptr + (size_t)(lrow + 32 * r) * INF + kn + lcol);
            }
        }

        #pragma unroll
        for (int kk = 0; kk < 4; kk++) {
            const uint32_t koff = (uint32_t)(kk * 8 * 4);   // 8 floats per step
            unsigned a[4][4], b[4][2];
            #pragma unroll
            for (int mi = 0; mi < 4; mi++)
                LDSM_X4(a[mi][0], a[mi][1], a[mi][2], a[mi][3], a_addr[mi] + koff);
            LDSM_X4(b[0][0], b[0][1], b[1][0], b[1][1], b_addr[0] + koff);
            LDSM_X4(b[2][0], b[2][1], b[3][0], b[3][1], b_addr[1] + koff);
            #pragma unroll
            for (int mi = 0; mi < 4; mi++)
                #pragma unroll
                for (int ni = 0; ni < 4; ni++)
                    mma_tf32(acc[mi][ni], a[mi], b[ni]);
        }
        __syncthreads();
    }

    // epilogue: bias + sigmoid, scatter to out[n][c][o]
    #pragma unroll
    for (int mi = 0; mi < 4; mi++) {
        const int m0 = mt * BM + wm * 64 + mi * 16;
        const int r0 = m0 + g, r1 = m0 + g + 8;
        #pragma unroll
        for (int ni = 0; ni < 4; ni++) {
            const int o0 = nt * BN + wn * 32 + ni * 8 + 2 * tig;
            const float bv0 = __ldg(bias + c * OUTF + o0);
            const float bv1 = __ldg(bias + c * OUTF + o0 + 1);
            float v00 = acc[mi][ni][0] + bv0;
            float v01 = acc[mi][ni][1] + bv1;
            float v10 = acc[mi][ni][2] + bv0;
            float v11 = acc[mi][ni][3] + bv1;
            out[((size_t)r0 * CCH + c) * OUTF + o0    ] = 1.f / (1.f + __expf(-v00));
            out[((size_t)r0 * CCH + c) * OUTF + o0 + 1] = 1.f / (1.f + __expf(-v01));
            out[((size_t)r1 * CCH + c) * OUTF + o0    ] = 1.f / (1.f + __expf(-v10));
            out[((size_t)r1 * CCH + c) * OUTF + o0 + 1] = 1.f / (1.f + __expf(-v11));
        }
    }
}

extern "C" void kernel_launch(void* const* d_in, const int* in_sizes, int n_in,
                              void* d_out, int out_size) {
    const float* x  = (const float*)d_in[0];
    const float* Wt = (const float*)d_in[1];
    const float* b  = (const float*)d_in[2];
    float* out = (float*)d_out;

    sort_rows<<<(NB * CCH) / 8, 256>>>(x);

    dim3 grid(OUTF / BN, NB / BM, CCH);
    gemm_tf32<<<grid, 256>>>(Wt, b, out);
}

// round 8
// speedup vs baseline: 2.4841x; 1.0920x over previous
#include <cuda_runtime.h>
#include <math.h>
#include <stdint.h>

#define NB   256   // batch
#define CCH  64    // channels
#define INF  1024  // in features
#define OUTF 1024  // out features

#define BM 128
#define BN 128
#define BK 32
#define SPAD 4
#define TSTRIDE (BK + SPAD)          // 36 floats
#define TILE_F  (BM * TSTRIDE)       // 4608 floats per matrix tile
#define STAGE_BYTES (2 * TILE_F * 4) // A+B per stage = 36864 B
#define NSTAGE 3
#define SMEM_BYTES (NSTAGE * STAGE_BYTES)  // 110592

// Scratch: sorted rows (tf32-pre-rounded), layout [c][n][x].
__device__ float g_sorted[(size_t)CCH * NB * INF];

__device__ __forceinline__ float f2tf(float f) {
    unsigned u;
    asm("cvt.rna.tf32.f32 %0, %1;" : "=r"(u) : "f"(f));
    return __uint_as_float(u);
}
__device__ __forceinline__ unsigned f2tf_u(unsigned u) {
    asm("cvt.rna.tf32.f32 %0, %1;" : "=r"(u) : "f"(__uint_as_float(u)));
    return u;
}

// ===========================================================================
// Sort: one warp per row, 32 elems/thread, fully-templated bitonic network.
// Writes tf32-rounded values (A-side cvt hoisted out of the GEMM).
// ===========================================================================
template<int K, int J>
__device__ __forceinline__ void bitonic_stage(float (&e)[32], int lane) {
    if constexpr (J >= 32) {
        constexpr int jj = J >> 5;
        const bool up       = ((lane << 5) & K) == 0;
        const bool lower    = (lane & jj) == 0;
        const bool keep_max = (up == lower);
        #pragma unroll
        for (int r = 0; r < 32; r++) {
            float v  = __shfl_xor_sync(0xffffffffu, e[r], jj);
            float mx = fmaxf(e[r], v);
            float mn = fminf(e[r], v);
            e[r] = keep_max ? mx : mn;
        }
    } else {
        bool up_lane = true;
        if constexpr (K >= 32) up_lane = (((lane << 5) & K) == 0);
        #pragma unroll
        for (int r = 0; r < 32; r++) {
            if ((r & J) == 0) {
                const int rr = r | J;
                bool up;
                if constexpr (K <= 16) up = ((r & K) == 0);
                else                   up = up_lane;
                float a = e[r], b = e[rr];
                float mx = fmaxf(a, b);
                float mn = fminf(a, b);
                e[r]  = up ? mx : mn;
                e[rr] = up ? mn : mx;
            }
        }
    }
}

template<int K, int J>
__device__ __forceinline__ void bitonic_merge(float (&e)[32], int lane) {
    bitonic_stage<K, J>(e, lane);
    if constexpr (J > 1) bitonic_merge<K, (J >> 1)>(e, lane);
}

template<int K>
__device__ __forceinline__ void bitonic_level(float (&e)[32], int lane) {
    bitonic_merge<K, (K >> 1)>(e, lane);
    if constexpr (K < 1024) bitonic_level<(K << 1)>(e, lane);
}

__global__ __launch_bounds__(256) void sort_rows(const float* __restrict__ x) {
    const int warp_global = blockIdx.x * (blockDim.x >> 5) + (threadIdx.x >> 5);
    const int lane = threadIdx.x & 31;
    const int n = warp_global / CCH;
    const int c = warp_global % CCH;

    const float* src = x + ((size_t)n * CCH + c) * INF;

    float e[32];
    {
        const float4* s4 = (const float4*)(src + lane * 32);
        #pragma unroll
        for (int q = 0; q < 8; q++) {
            float4 v = s4[q];
            e[q * 4 + 0] = v.x; e[q * 4 + 1] = v.y;
            e[q * 4 + 2] = v.z; e[q * 4 + 3] = v.w;
        }
    }

    bitonic_level<2>(e, lane);

    float* dst = g_sorted + ((size_t)c * NB + n) * INF + lane * 32;
    {
        float4* d4 = (float4*)dst;
        #pragma unroll
        for (int q = 0; q < 8; q++) {
            float4 v;
            v.x = f2tf(e[q * 4 + 0]); v.y = f2tf(e[q * 4 + 1]);
            v.z = f2tf(e[q * 4 + 2]); v.w = f2tf(e[q * 4 + 3]);
            d4[q] = v;
        }
    }
}

// ===========================================================================
// Per-channel GEMM, tf32 mma.sync m16n8k8, ldmatrix fragment loads,
// cp.async 3-stage pipeline, ONE barrier per K-tile.
// ===========================================================================
__device__ __forceinline__ void mma_tf32(float* d, const unsigned* a, const unsigned* b) {
    asm volatile(
        "mma.sync.aligned.m16n8k8.row.col.f32.tf32.tf32.f32 "
        "{%0,%1,%2,%3}, {%4,%5,%6,%7}, {%8,%9}, {%0,%1,%2,%3};\n"
        : "+f"(d[0]), "+f"(d[1]), "+f"(d[2]), "+f"(d[3])
        : "r"(a[0]), "r"(a[1]), "r"(a[2]), "r"(a[3]),
          "r"(b[0]), "r"(b[1]));
}

#define LDSM_X4(r0, r1, r2, r3, addr)                                          \
    asm volatile("ldmatrix.sync.aligned.m8n8.x4.shared.b16 {%0,%1,%2,%3}, [%4];" \
                 : "=r"(r0), "=r"(r1), "=r"(r2), "=r"(r3) : "r"(addr))

#define CP_ASYNC16(dst, src)                                                   \
    asm volatile("cp.async.cg.shared.global [%0], [%1], 16;\n"                 \
                 :: "r"(dst), "l"(src))

__device__ __forceinline__ uint32_t smem_u32(const void* p) {
    uint32_t a;
    asm("{ .reg .u64 t; cvta.to.shared.u64 t, %1; cvt.u32.u64 %0, t; }" : "=r"(a) : "l"(p));
    return a;
}

__global__ __launch_bounds__(256, 2) void gemm_tf32(const float* __restrict__ Wt,
                                                    const float* __restrict__ bias,
                                                    float* __restrict__ out) {
    extern __shared__ float smem[];

    const int c  = blockIdx.z;
    const int mt = blockIdx.y;   // 0..1
    const int nt = blockIdx.x;   // 0..7

    const float* Aptr = g_sorted + ((size_t)c * NB + (size_t)mt * BM) * INF;
    const float* Bptr = Wt + ((size_t)c * OUTF + (size_t)nt * BN) * INF;

    const int tid  = threadIdx.x;
    const int warp = tid >> 5, lane = tid & 31;
    const int wm = warp >> 2, wn = warp & 3;     // 2 x 4 warp grid
    const int g = lane >> 2, tig = lane & 3;

    float acc[4][4][4];
    #pragma unroll
    for (int mi = 0; mi < 4; mi++)
        #pragma unroll
        for (int ni = 0; ni < 4; ni++)
            #pragma unroll
            for (int q = 0; q < 4; q++) acc[mi][ni][q] = 0.f;

    const uint32_t S_base = smem_u32(smem);        // stage 0, A region
    // loader mapping: 4 cp.async per matrix per stage per thread
    const int lrow = tid >> 3;          // 0..31
    const int lcol = (tid & 7) << 2;    // 0,4,...,28
    // per-thread smem byte offsets within a stage (A region; B adds TILE_F*4)
    uint32_t st_off[4];
    #pragma unroll
    for (int r = 0; r < 4; r++)
        st_off[r] = (uint32_t)(((lrow + 32 * r) * TSTRIDE + lcol) * 4);

    // ldmatrix per-lane addresses (stage-0 base; add stage byte offset)
    const int a_row = (lane & 7) + ((lane >> 3) & 1) * 8;
    const int a_kq  = (lane >> 4) * 4;
    uint32_t a_addr[4];
    #pragma unroll
    for (int mi = 0; mi < 4; mi++)
        a_addr[mi] = S_base + (uint32_t)(((wm * 64 + mi * 16 + a_row) * TSTRIDE + a_kq) * 4);
    const int b_q   = lane >> 3;
    const int b_row = (lane & 7) + (b_q >> 1) * 8;
    const int b_kq  = (b_q & 1) * 4;
    uint32_t b_addr[2];
    #pragma unroll
    for (int nj = 0; nj < 2; nj++)
        b_addr[nj] = S_base + (uint32_t)(TILE_F * 4) +
                     (uint32_t)(((wn * 32 + nj * 16 + b_row) * TSTRIDE + b_kq) * 4);

#define ISSUE_LOADS(t, stage)                                                  \
    {                                                                          \
        const float* Ak = Aptr + (t) * BK + lcol;                              \
        const float* Bk = Bptr + (t) * BK + lcol;                              \
        const uint32_t ab = S_base + (uint32_t)(stage) * STAGE_BYTES;          \
        const uint32_t bb = ab + (uint32_t)(TILE_F * 4);                       \
        _Pragma("unroll")                                                      \
        for (int r = 0; r < 4; r++) {                                          \
            CP_ASYNC16(ab + st_off[r], Ak + (size_t)(lrow + 32 * r) * INF);    \
            CP_ASYNC16(bb + st_off[r], Bk + (size_t)(lrow + 32 * r) * INF);    \
        }                                                                      \
    }

    // ---- prologue: stages 0 and 1 in flight ----
    ISSUE_LOADS(0, 0);
    asm volatile("cp.async.commit_group;\n" ::: "memory");
    ISSUE_LOADS(1, 1);
    asm volatile("cp.async.commit_group;\n" ::: "memory");

    const int NT = INF / BK;   // 32
    int st = 0;                // stage holding tile t
    for (int t = 0; t < NT; t++) {
        asm volatile("cp.async.wait_group 1;\n" ::: "memory");  // tile t arrived
        __syncthreads();   // data visible to all; all warps done with MMA(t-1)

        // issue loads for tile t+2 into the stage MMA(t-1) just freed
        if (t + 2 < NT) {
            int ls = st + 2; if (ls >= NSTAGE) ls -= NSTAGE;
            ISSUE_LOADS(t + 2, ls);
        }
        asm volatile("cp.async.commit_group;\n" ::: "memory");

        const uint32_t soff = (uint32_t)st * STAGE_BYTES;
        #pragma unroll
        for (int kk = 0; kk < 4; kk++) {
            const uint32_t koff = soff + (uint32_t)(kk * 8 * 4);
            unsigned a[4][4], b[4][2];
            #pragma unroll
            for (int mi = 0; mi < 4; mi++)
                LDSM_X4(a[mi][0], a[mi][1], a[mi][2], a[mi][3], a_addr[mi] + koff);
            LDSM_X4(b[0][0], b[0][1], b[1][0], b[1][1], b_addr[0] + koff);
            LDSM_X4(b[2][0], b[2][1], b[3][0], b[3][1], b_addr[1] + koff);
            // B loaded raw fp32 -> round to tf32 in registers (rna)
            #pragma unroll
            for (int ni = 0; ni < 4; ni++) {
                b[ni][0] = f2tf_u(b[ni][0]);
                b[ni][1] = f2tf_u(b[ni][1]);
            }
            #pragma unroll
            for (int mi = 0; mi < 4; mi++)
                #pragma unroll
                for (int ni = 0; ni < 4; ni++)
                    mma_tf32(acc[mi][ni], a[mi], b[ni]);
        }

        st++; if (st == NSTAGE) st = 0;
    }

    // epilogue: bias + sigmoid, scatter to out[n][c][o]
    #pragma unroll
    for (int mi = 0; mi < 4; mi++) {
        const int m0 = mt * BM + wm * 64 + mi * 16;
        const int r0 = m0 + g, r1 = m0 + g + 8;
        #pragma unroll
        for (int ni = 0; ni < 4; ni++) {
            const int o0 = nt * BN + wn * 32 + ni * 8 + 2 * tig;
            const float bv0 = __ldg(bias + c * OUTF + o0);
            const float bv1 = __ldg(bias + c * OUTF + o0 + 1);
            float v00 = acc[mi][ni][0] + bv0;
            float v01 = acc[mi][ni][1] + bv1;
            float v10 = acc[mi][ni][2] + bv0;
            float v11 = acc[mi][ni][3] + bv1;
            out[((size_t)r0 * CCH + c) * OUTF + o0    ] = 1.f / (1.f + __expf(-v00));
            out[((size_t)r0 * CCH + c) * OUTF + o0 + 1] = 1.f / (1.f + __expf(-v01));
            out[((size_t)r1 * CCH + c) * OUTF + o0    ] = 1.f / (1.f + __expf(-v10));
            out[((size_t)r1 * CCH + c) * OUTF + o0 + 1] = 1.f / (1.f + __expf(-v11));
        }
    }
}

extern "C" void kernel_launch(void* const* d_in, const int* in_sizes, int n_in,
                              void* d_out, int out_size) {
    const float* x  = (const float*)d_in[0];
    const float* Wt = (const float*)d_in[1];
    const float* b  = (const float*)d_in[2];
    float* out = (float*)d_out;

    sort_rows<<<(NB * CCH) / 8, 256>>>(x);

    static bool attr_set = false;
    if (!attr_set) {
        cudaFuncSetAttribute(gemm_tf32, cudaFuncAttributeMaxDynamicSharedMemorySize,
                             SMEM_BYTES);
        attr_set = true;
    }

    dim3 grid(OUTF / BN, NB / BM, CCH);
    gemm_tf32<<<grid, 256, SMEM_BYTES>>>(Wt, b, out);
}